// round 2
// baseline (speedup 1.0000x reference)
#include <cuda_runtime.h>

// Fixed problem shapes.
#define Bc   2
#define Tc   2048
#define Dc   1024
#define Hc   16
#define NDc  64
#define BHc  (Bc*Hc)
#define QCH  8          // q-chunks for two-stage column sum (Tc/256)

// Static device scratch.
__device__ float g_QH[BHc * Tc * NDc];          // [bh][t][nd]
__device__ float g_KH[BHc * Tc * NDc];
__device__ float g_VH[BHc * Tc * NDc];          // scaled in-place by inv[k]
__device__ float g_O [Bc * Tc * Dc];            // [B,T,D]
__device__ float g_inv[BHc * Tc];               // 1 / column-sum
__device__ float g_part[BHc * QCH * Tc];        // partial column sums
__device__ float g_E[(size_t)BHc * Tc * Tc];    // exp(z), lower tile-band written

// ---------------------------------------------------------------------------
// Y = X @ W^T + bias.  M x 1024 times (1024 x 1024)^T.
// 128x128 tile, BK=16, 256 threads, 8x8 per thread.
// split=1: scatter to per-head layout [bh][t][nd].
// ---------------------------------------------------------------------------
__global__ __launch_bounds__(256, 2)
void proj128(const float* __restrict__ X, const float* __restrict__ W,
             const float* __restrict__ bias, float* __restrict__ Y, int split)
{
    __shared__ __align__(16) float As[16][132];
    __shared__ __align__(16) float Bs[16][132];
    const int bm = blockIdx.y * 128;
    const int bn = blockIdx.x * 128;
    const int tid = threadIdx.x;
    const int tx = tid & 15, ty = tid >> 4;
    const int ar = tid >> 2, ac = tid & 3;      // 64 rows x 4 float4-cols
    float acc[8][8] = {};

    for (int k0 = 0; k0 < Dc; k0 += 16) {
        #pragma unroll
        for (int h = 0; h < 2; h++) {
            int r = ar + h * 64;
            float4 va = *(const float4*)&X[(size_t)(bm + r) * Dc + k0 + ac * 4];
            As[ac*4+0][r] = va.x; As[ac*4+1][r] = va.y;
            As[ac*4+2][r] = va.z; As[ac*4+3][r] = va.w;
            float4 vb = *(const float4*)&W[(size_t)(bn + r) * Dc + k0 + ac * 4];
            Bs[ac*4+0][r] = vb.x; Bs[ac*4+1][r] = vb.y;
            Bs[ac*4+2][r] = vb.z; Bs[ac*4+3][r] = vb.w;
        }
        __syncthreads();
        #pragma unroll
        for (int kk = 0; kk < 16; kk++) {
            float a[8], b[8];
            *(float4*)&a[0] = *(const float4*)&As[kk][ty*8];
            *(float4*)&a[4] = *(const float4*)&As[kk][ty*8+4];
            *(float4*)&b[0] = *(const float4*)&Bs[kk][tx*8];
            *(float4*)&b[4] = *(const float4*)&Bs[kk][tx*8+4];
            #pragma unroll
            for (int i = 0; i < 8; i++)
                #pragma unroll
                for (int j = 0; j < 8; j++)
                    acc[i][j] += a[i] * b[j];
        }
        __syncthreads();
    }

    #pragma unroll
    for (int i = 0; i < 8; i++) {
        int m = bm + ty * 8 + i;
        #pragma unroll
        for (int j = 0; j < 8; j++) {
            int n = bn + tx * 8 + j;
            float v = acc[i][j] + bias[n];
            if (split) {
                int b = m >> 11, t = m & (Tc - 1);
                int h = n >> 6,  d = n & (NDc - 1);
                Y[(size_t)((b * Hc + h) * Tc + t) * NDc + d] = v;
            } else {
                Y[(size_t)m * Dc + n] = v;
            }
        }
    }
}

// ---------------------------------------------------------------------------
// E[q][k] = exp(qh[q].kh[k] / 8) for k<=q (0 above diag in diagonal tiles).
// 128x128 tile, K=64. Tiles with kt>qt skipped (never read downstream).
// ---------------------------------------------------------------------------
__global__ __launch_bounds__(256, 2)
void score128()
{
    const int kt = blockIdx.x, qt = blockIdx.y, bh = blockIdx.z;
    if (kt > qt) return;

    const float* Qp = g_QH + (size_t)bh * Tc * NDc;
    const float* Kp = g_KH + (size_t)bh * Tc * NDc;
    float*       Ep = g_E  + (size_t)bh * Tc * Tc;

    __shared__ __align__(16) float As[16][132];
    __shared__ __align__(16) float Bs[16][132];
    const int tid = threadIdx.x;
    const int tx = tid & 15, ty = tid >> 4;
    const int ar = tid >> 2, ac = tid & 3;
    float acc[8][8] = {};

    #pragma unroll
    for (int k0 = 0; k0 < NDc; k0 += 16) {
        #pragma unroll
        for (int h = 0; h < 2; h++) {
            int r = ar + h * 64;
            float4 va = *(const float4*)&Qp[(size_t)(qt*128 + r) * NDc + k0 + ac*4];
            As[ac*4+0][r] = va.x; As[ac*4+1][r] = va.y;
            As[ac*4+2][r] = va.z; As[ac*4+3][r] = va.w;
            float4 vb = *(const float4*)&Kp[(size_t)(kt*128 + r) * NDc + k0 + ac*4];
            Bs[ac*4+0][r] = vb.x; Bs[ac*4+1][r] = vb.y;
            Bs[ac*4+2][r] = vb.z; Bs[ac*4+3][r] = vb.w;
        }
        __syncthreads();
        #pragma unroll
        for (int kk = 0; kk < 16; kk++) {
            float a[8], b[8];
            *(float4*)&a[0] = *(const float4*)&As[kk][ty*8];
            *(float4*)&a[4] = *(const float4*)&As[kk][ty*8+4];
            *(float4*)&b[0] = *(const float4*)&Bs[kk][tx*8];
            *(float4*)&b[4] = *(const float4*)&Bs[kk][tx*8+4];
            #pragma unroll
            for (int i = 0; i < 8; i++)
                #pragma unroll
                for (int j = 0; j < 8; j++)
                    acc[i][j] += a[i] * b[j];
        }
        __syncthreads();
    }

    #pragma unroll
    for (int i = 0; i < 8; i++) {
        int q = qt * 128 + ty * 8 + i;
        #pragma unroll
        for (int j = 0; j < 8; j++) {
            int kcol = kt * 128 + tx * 8 + j;
            float v = (kcol <= q) ? __expf(acc[i][j] * 0.125f) : 0.0f;
            Ep[(size_t)q * Tc + kcol] = v;
        }
    }
}

// ---------------------------------------------------------------------------
// Stage 1: partial column sums over 256-row q-chunks (deterministic).
// ---------------------------------------------------------------------------
__global__ __launch_bounds__(256)
void colsum1()
{
    const int bh = blockIdx.z;
    const int qc = blockIdx.y;
    const int k  = blockIdx.x * 256 + threadIdx.x;
    const float* Ep = g_E + (size_t)bh * Tc * Tc;
    const int qlo0 = k & ~127;                 // first written row for col k
    int qlo = qc * 256; if (qlo < qlo0) qlo = qlo0;
    const int qhi = qc * 256 + 256;
    float s = 0.0f;
    for (int q = qlo; q < qhi; q++)
        s += Ep[(size_t)q * Tc + k];
    g_part[(bh * QCH + qc) * Tc + k] = s;
}

// Stage 2: inv[k] = 1 / sum of partials (fixed order -> deterministic).
__global__ __launch_bounds__(256)
void colsum2()
{
    const int bh = blockIdx.y;
    const int k  = blockIdx.x * 256 + threadIdx.x;
    float s = 0.0f;
    #pragma unroll
    for (int qc = 0; qc < QCH; qc++)
        s += g_part[(bh * QCH + qc) * Tc + k];
    g_inv[bh * Tc + k] = 1.0f / s;
}

// V'[k][d] = inv[k] * V[k][d]  (in place).
__global__ __launch_bounds__(256)
void vscale()
{
    size_t idx = (size_t)blockIdx.x * 256 + threadIdx.x;   // over BHc*Tc*NDc
    g_VH[idx] *= g_inv[idx >> 6];
}

// ---------------------------------------------------------------------------
// O[q][hd] = sum_{k tiles <= qt} E[q][k] * V'[k][d].
// Tile 128(q) x 64(d), BK=16, 256 threads, 4x8 per thread.
// ---------------------------------------------------------------------------
__global__ __launch_bounds__(256, 2)
void attnv128()
{
    const int qt = blockIdx.x, bh = blockIdx.y;
    const float* Ep = g_E  + (size_t)bh * Tc * Tc;
    const float* Vp = g_VH + (size_t)bh * Tc * NDc;

    __shared__ __align__(16) float Es[16][132];
    __shared__ __align__(16) float Vs[16][68];
    const int tid = threadIdx.x;
    const int tx = tid & 7, ty = tid >> 3;      // 8 x 32
    const int er = tid >> 2, ec = tid & 3;      // E: 64 rows x 4 f4-cols
    const int vr = tid >> 4, vc = tid & 15;     // V: 16 rows x 16 f4-cols
    float acc[4][8] = {};

    const int kmax = (qt + 1) * 128;
    for (int k0 = 0; k0 < kmax; k0 += 16) {
        #pragma unroll
        for (int h = 0; h < 2; h++) {
            int r = er + h * 64;
            float4 va = *(const float4*)&Ep[(size_t)(qt*128 + r) * Tc + k0 + ec*4];
            Es[ec*4+0][r] = va.x; Es[ec*4+1][r] = va.y;
            Es[ec*4+2][r] = va.z; Es[ec*4+3][r] = va.w;
        }
        *(float4*)&Vs[vr][vc*4] = *(const float4*)&Vp[(size_t)(k0 + vr) * NDc + vc*4];
        __syncthreads();
        #pragma unroll
        for (int kk = 0; kk < 16; kk++) {
            float a[4], b[8];
            *(float4*)&a[0] = *(const float4*)&Es[kk][ty*4];
            *(float4*)&b[0] = *(const float4*)&Vs[kk][tx*8];
            *(float4*)&b[4] = *(const float4*)&Vs[kk][tx*8+4];
            #pragma unroll
            for (int i = 0; i < 4; i++)
                #pragma unroll
                for (int j = 0; j < 8; j++)
                    acc[i][j] += a[i] * b[j];
        }
        __syncthreads();
    }

    const int b = bh >> 4, h = bh & (Hc - 1);
    #pragma unroll
    for (int i = 0; i < 4; i++) {
        int q = qt * 128 + ty * 4 + i;
        #pragma unroll
        for (int j = 0; j < 8; j++) {
            int d = tx * 8 + j;
            g_O[(size_t)(b * Tc + q) * Dc + h * NDc + d] = acc[i][j];
        }
    }
}

// ---------------------------------------------------------------------------
extern "C" void kernel_launch(void* const* d_in, const int* in_sizes, int n_in,
                              void* d_out, int out_size)
{
    const float* q  = (const float*)d_in[0];
    const float* k  = (const float*)d_in[1];
    const float* v  = (const float*)d_in[2];
    const float* Wq = (const float*)d_in[3];
    const float* bq = (const float*)d_in[4];
    const float* Wk = (const float*)d_in[5];
    const float* bk = (const float*)d_in[6];
    const float* Wv = (const float*)d_in[7];
    const float* bv = (const float*)d_in[8];
    const float* Wc = (const float*)d_in[9];
    const float* bc = (const float*)d_in[10];
    float* out = (float*)d_out;

    float *pQH, *pKH, *pVH, *pO;
    cudaGetSymbolAddress((void**)&pQH, g_QH);
    cudaGetSymbolAddress((void**)&pKH, g_KH);
    cudaGetSymbolAddress((void**)&pVH, g_VH);
    cudaGetSymbolAddress((void**)&pO,  g_O);

    dim3 tpb(256);
    dim3 gproj(Dc / 128, (Bc * Tc) / 128);            // 8 x 32

    proj128<<<gproj, tpb>>>(q, Wq, bq, pQH, 1);
    proj128<<<gproj, tpb>>>(k, Wk, bk, pKH, 1);
    proj128<<<gproj, tpb>>>(v, Wv, bv, pVH, 1);

    score128<<<dim3(Tc/128, Tc/128, BHc), tpb>>>();   // 16 x 16 x 32
    colsum1<<<dim3(Tc/256, QCH, BHc), tpb>>>();
    colsum2<<<dim3(Tc/256, BHc), tpb>>>();
    vscale<<<(BHc*Tc*NDc)/256, tpb>>>();
    attnv128<<<dim3(Tc/128, BHc), tpb>>>();

    proj128<<<gproj, tpb>>>(pO, Wc, bc, out, 0);
}

// round 4
// speedup vs baseline: 5.3579x; 5.3579x over previous
#include <cuda_runtime.h>
#include <cuda_fp16.h>
#include <stdint.h>

#define Tc  2048
#define Dc  1024
#define Hc  16
#define BHc 32

// ---------------- static device scratch ----------------
__device__ __half g_X [4096*1024];            // current GEMM input, fp16
__device__ __half g_W [1024*1024];            // current weight, fp16
__device__ __half g_QH[BHc*Tc*64];            // [bh][t][nd] fp16
__device__ __half g_KH[BHc*Tc*64];
__device__ float  g_V [BHc*Tc*64];            // V heads fp32
__device__ __half g_VT[BHc*64*Tc];            // [bh][d][k], scaled by inv[k]
__device__ float  g_O [4096*1024];            // attention output [B,T,D]
__device__ float  g_part[BHc*16*Tc];          // per-(bh,qt) column partial sums
__device__ float  g_inv [BHc*Tc];
__device__ __half g_E[(size_t)BHc*Tc*Tc];     // exp(z), fp16, lower tile-band

// ---------------- warp MMA helpers ----------------
static __device__ __forceinline__ void mma16816(float* d, const uint32_t* a,
                                                const uint32_t* b) {
  asm volatile(
    "mma.sync.aligned.m16n8k16.row.col.f32.f16.f16.f32 "
    "{%0,%1,%2,%3}, {%4,%5,%6,%7}, {%8,%9}, {%0,%1,%2,%3};"
    : "+f"(d[0]), "+f"(d[1]), "+f"(d[2]), "+f"(d[3])
    : "r"(a[0]), "r"(a[1]), "r"(a[2]), "r"(a[3]), "r"(b[0]), "r"(b[1]));
}
static __device__ __forceinline__ void ldsm4(uint32_t* r, const void* p) {
  uint32_t a = (uint32_t)__cvta_generic_to_shared(p);
  asm volatile("ldmatrix.sync.aligned.m8n8.x4.shared.b16 {%0,%1,%2,%3}, [%4];"
               : "=r"(r[0]), "=r"(r[1]), "=r"(r[2]), "=r"(r[3]) : "r"(a));
}

// ---------------- fp32 -> fp16 converter ----------------
__global__ __launch_bounds__(256)
void cvt_half(const float* __restrict__ src, __half* __restrict__ dst)
{
  size_t i = ((size_t)blockIdx.x * 256 + threadIdx.x) * 8;
  float4 a = *(const float4*)(src + i);
  float4 b = *(const float4*)(src + i + 4);
  __half2 h0 = __floats2half2_rn(a.x, a.y), h1 = __floats2half2_rn(a.z, a.w);
  __half2 h2 = __floats2half2_rn(b.x, b.y), h3 = __floats2half2_rn(b.z, b.w);
  uint4 u;
  u.x = *(uint32_t*)&h0; u.y = *(uint32_t*)&h1;
  u.z = *(uint32_t*)&h2; u.w = *(uint32_t*)&h3;
  *(uint4*)(dst + i) = u;
}

// ---------------- projection GEMM: Y = X @ W^T + b ----------------
// 128x128 tile, 8 warps (2m x 4n), warp tile 64x32, K-chunk 32.
// mode 0: fp32 out [m][n];  1/2: fp16 Q/K per-head scatter;  3: fp32 V scatter.
__global__ __launch_bounds__(256)
void proj_tc(const float* __restrict__ bias, float* __restrict__ outp, int mode)
{
  __shared__ __align__(16) __half As[128][40];
  __shared__ __align__(16) __half Bs[128][40];
  const int tid = threadIdx.x, lane = tid & 31, wid = tid >> 5;
  const int bn = blockIdx.x * 128, bm = blockIdx.y * 128;
  const int wm = (wid >> 2) * 64, wn = (wid & 3) * 32;

  float acc[4][4][4] = {};
  uint4 pa[2], pb[2];

  #pragma unroll
  for (int i = 0; i < 2; i++) {
    int u = tid + i * 256, r = u >> 2, c = u & 3;
    pa[i] = *(const uint4*)(g_X + (size_t)(bm + r) * 1024 + c * 8);
    pb[i] = *(const uint4*)(g_W + (size_t)(bn + r) * 1024 + c * 8);
  }

  for (int ch = 0; ch < 32; ch++) {
    #pragma unroll
    for (int i = 0; i < 2; i++) {
      int u = tid + i * 256, r = u >> 2, c = u & 3;
      *(uint4*)&As[r][c * 8] = pa[i];
      *(uint4*)&Bs[r][c * 8] = pb[i];
    }
    __syncthreads();
    if (ch < 31) {
      const int kb = (ch + 1) * 32;
      #pragma unroll
      for (int i = 0; i < 2; i++) {
        int u = tid + i * 256, r = u >> 2, c = u & 3;
        pa[i] = *(const uint4*)(g_X + (size_t)(bm + r) * 1024 + kb + c * 8);
        pb[i] = *(const uint4*)(g_W + (size_t)(bn + r) * 1024 + kb + c * 8);
      }
    }
    #pragma unroll
    for (int k16 = 0; k16 < 2; k16++) {
      uint32_t aF[4][4], bF[2][4];
      #pragma unroll
      for (int mf = 0; mf < 4; mf++)
        ldsm4(aF[mf], &As[wm + mf * 16 + (lane & 15)][k16 * 16 + (lane >> 4) * 8]);
      #pragma unroll
      for (int nh = 0; nh < 2; nh++)
        ldsm4(bF[nh], &Bs[wn + nh * 16 + (lane & 15)][k16 * 16 + (lane >> 4) * 8]);
      #pragma unroll
      for (int mf = 0; mf < 4; mf++)
        #pragma unroll
        for (int nf = 0; nf < 4; nf++) {
          uint32_t bb[2] = { bF[nf >> 1][nf & 1], bF[nf >> 1][(nf & 1) + 2] };
          mma16816(acc[mf][nf], aF[mf], bb);
        }
    }
    __syncthreads();
  }

  #pragma unroll
  for (int mf = 0; mf < 4; mf++) {
    int row0 = bm + wm + mf * 16 + (lane >> 2);
    #pragma unroll
    for (int nf = 0; nf < 4; nf++) {
      int col = bn + wn + nf * 8 + (lane & 3) * 2;
      float b0 = bias[col], b1 = bias[col + 1];
      #pragma unroll
      for (int h = 0; h < 2; h++) {
        int row = row0 + h * 8;
        float v0 = acc[mf][nf][h * 2 + 0] + b0;
        float v1 = acc[mf][nf][h * 2 + 1] + b1;
        if (mode == 0) {
          *(float2*)(outp + (size_t)row * 1024 + col) = make_float2(v0, v1);
        } else {
          int b = row >> 11, t = row & (Tc - 1), hh = col >> 6, d = col & 63;
          size_t base = ((size_t)(b * Hc + hh) * Tc + t) * 64 + d;
          if (mode == 3) {
            *(float2*)(g_V + base) = make_float2(v0, v1);
          } else {
            __half2 hv = __floats2half2_rn(v0, v1);
            *(__half2*)((mode == 1 ? g_QH : g_KH) + base) = hv;
          }
        }
      }
    }
  }
}

// ---------------- scores: E = exp(QK^T/8) masked + fused column partials ----
__global__ __launch_bounds__(256)
void score_tc()
{
  const int kt = blockIdx.x, qt = blockIdx.y, bh = blockIdx.z;
  if (kt > qt) return;
  __shared__ __align__(16) __half Qs[128][72];
  __shared__ __align__(16) __half Ks[128][72];
  __shared__ float cs[16][128];
  const int tid = threadIdx.x, lane = tid & 31, wid = tid >> 5;
  const int wm = (wid >> 2) * 64, wn = (wid & 3) * 32;
  const size_t hb = (size_t)bh * Tc * 64;

  #pragma unroll
  for (int i = 0; i < 4; i++) {
    int u = tid + i * 256, r = u >> 3, c = u & 7;
    *(uint4*)&Qs[r][c * 8] = *(const uint4*)(g_QH + hb + (size_t)(qt * 128 + r) * 64 + c * 8);
    *(uint4*)&Ks[r][c * 8] = *(const uint4*)(g_KH + hb + (size_t)(kt * 128 + r) * 64 + c * 8);
  }
  __syncthreads();

  float acc[4][4][4] = {};
  #pragma unroll
  for (int k16 = 0; k16 < 4; k16++) {
    uint32_t aF[4][4], bF[2][4];
    #pragma unroll
    for (int mf = 0; mf < 4; mf++)
      ldsm4(aF[mf], &Qs[wm + mf * 16 + (lane & 15)][k16 * 16 + (lane >> 4) * 8]);
    #pragma unroll
    for (int nh = 0; nh < 2; nh++)
      ldsm4(bF[nh], &Ks[wn + nh * 16 + (lane & 15)][k16 * 16 + (lane >> 4) * 8]);
    #pragma unroll
    for (int mf = 0; mf < 4; mf++)
      #pragma unroll
      for (int nf = 0; nf < 4; nf++) {
        uint32_t bb[2] = { bF[nf >> 1][nf & 1], bF[nf >> 1][(nf & 1) + 2] };
        mma16816(acc[mf][nf], aF[mf], bb);
      }
  }

  float csp[4][2] = {};
  #pragma unroll
  for (int mf = 0; mf < 4; mf++) {
    #pragma unroll
    for (int nf = 0; nf < 4; nf++) {
      int k0 = kt * 128 + wn + nf * 8 + (lane & 3) * 2;
      #pragma unroll
      for (int h = 0; h < 2; h++) {
        int q = qt * 128 + wm + mf * 16 + (lane >> 2) + h * 8;
        float e0 = (k0     <= q) ? __expf(acc[mf][nf][h*2+0] * 0.125f) : 0.0f;
        float e1 = (k0 + 1 <= q) ? __expf(acc[mf][nf][h*2+1] * 0.125f) : 0.0f;
        __half2 hv = __floats2half2_rn(e0, e1);
        *(__half2*)(g_E + ((size_t)bh * Tc + q) * Tc + k0) = hv;
        csp[nf][0] += e0;
        csp[nf][1] += e1;
      }
    }
  }
  int rg = (wid >> 2) * 8 + (lane >> 2);
  #pragma unroll
  for (int nf = 0; nf < 4; nf++) {
    cs[rg][wn + nf * 8 + (lane & 3) * 2 + 0] = csp[nf][0];
    cs[rg][wn + nf * 8 + (lane & 3) * 2 + 1] = csp[nf][1];
  }
  __syncthreads();
  if (tid < 128) {
    float s = 0.0f;
    #pragma unroll
    for (int i = 0; i < 16; i++) s += cs[i][tid];
    g_part[(bh * 16 + qt) * Tc + kt * 128 + tid] = s;
  }
}

// inv[k] = 1 / sum over valid q-tiles (fixed order -> deterministic)
__global__ __launch_bounds__(256)
void colsum2()
{
  const int bh = blockIdx.y;
  const int k = blockIdx.x * 256 + threadIdx.x;
  const int qt0 = k >> 7;
  float s = 0.0f;
  for (int qt = qt0; qt < 16; qt++)
    s += g_part[(bh * 16 + qt) * Tc + k];
  g_inv[bh * Tc + k] = 1.0f / s;
}

// VT[bh][d][k] = fp16( V[bh][k][d] * inv[k] )
__global__ __launch_bounds__(256)
void vtrans()
{
  const int bh = blockIdx.y, k0 = blockIdx.x * 64;
  __shared__ float ts[64][65];
  const int tid = threadIdx.x, dl = tid & 63, kq = tid >> 6;
  #pragma unroll
  for (int i = 0; i < 16; i++) {
    int kk = i * 4 + kq;
    ts[kk][dl] = g_V[((size_t)bh * Tc + k0 + kk) * 64 + dl] * g_inv[bh * Tc + k0 + kk];
  }
  __syncthreads();
  #pragma unroll
  for (int i = 0; i < 16; i++) {
    int d = i * 4 + kq;
    g_VT[((size_t)bh * 64 + d) * Tc + k0 + dl] = __float2half(ts[dl][d]);
  }
}

// ---------------- O = E' @ V' ----------------
// block: q-tile 128 x d 64, 8 warps (4m x 2n), warp 32x32, K-chunk 64.
__global__ __launch_bounds__(256)
void attnv_tc()
{
  const int qt = (int)gridDim.x - 1 - (int)blockIdx.x;   // longest first
  const int bh = blockIdx.y;
  __shared__ __align__(16) __half Es[128][72];
  __shared__ __align__(16) __half Vs[64][72];
  const int tid = threadIdx.x, lane = tid & 31, wid = tid >> 5;
  const int wm = (wid >> 1) * 32, wn = (wid & 1) * 32;
  const __half* Ep = g_E  + (size_t)bh * Tc * Tc;
  const __half* Vp = g_VT + (size_t)bh * 64 * Tc;

  float acc[2][4][4] = {};
  const int nch = (qt + 1) * 2;
  for (int ch = 0; ch < nch; ch++) {
    const int kb = ch * 64;
    #pragma unroll
    for (int i = 0; i < 4; i++) {
      int u = tid + i * 256, r = u >> 3, c = u & 7;
      *(uint4*)&Es[r][c * 8] = *(const uint4*)(Ep + (size_t)(qt * 128 + r) * Tc + kb + c * 8);
    }
    #pragma unroll
    for (int i = 0; i < 2; i++) {
      int u = tid + i * 256, r = u >> 3, c = u & 7;
      *(uint4*)&Vs[r][c * 8] = *(const uint4*)(Vp + (size_t)r * Tc + kb + c * 8);
    }
    __syncthreads();
    #pragma unroll
    for (int k16 = 0; k16 < 4; k16++) {
      uint32_t aF[2][4], bF[2][4];
      #pragma unroll
      for (int mf = 0; mf < 2; mf++)
        ldsm4(aF[mf], &Es[wm + mf * 16 + (lane & 15)][k16 * 16 + (lane >> 4) * 8]);
      #pragma unroll
      for (int nh = 0; nh < 2; nh++)
        ldsm4(bF[nh], &Vs[wn + nh * 16 + (lane & 15)][k16 * 16 + (lane >> 4) * 8]);
      #pragma unroll
      for (int mf = 0; mf < 2; mf++)
        #pragma unroll
        for (int nf = 0; nf < 4; nf++) {
          uint32_t bb[2] = { bF[nf >> 1][nf & 1], bF[nf >> 1][(nf & 1) + 2] };
          mma16816(acc[mf][nf], aF[mf], bb);
        }
    }
    __syncthreads();
  }

  const int b = bh >> 4, h = bh & 15;
  #pragma unroll
  for (int mf = 0; mf < 2; mf++) {
    #pragma unroll
    for (int nf = 0; nf < 4; nf++) {
      int d = wn + nf * 8 + (lane & 3) * 2;
      #pragma unroll
      for (int hh = 0; hh < 2; hh++) {
        int q = qt * 128 + wm + mf * 16 + (lane >> 2) + hh * 8;
        *(float2*)(g_O + ((size_t)(b * Tc + q)) * 1024 + h * 64 + d) =
          make_float2(acc[mf][nf][hh*2+0], acc[mf][nf][hh*2+1]);
      }
    }
  }
}

// ---------------------------------------------------------------------------
extern "C" void kernel_launch(void* const* d_in, const int* in_sizes, int n_in,
                              void* d_out, int out_size)
{
  const float* q  = (const float*)d_in[0];
  const float* k  = (const float*)d_in[1];
  const float* v  = (const float*)d_in[2];
  const float* Wq = (const float*)d_in[3];
  const float* bq = (const float*)d_in[4];
  const float* Wk = (const float*)d_in[5];
  const float* bk = (const float*)d_in[6];
  const float* Wv = (const float*)d_in[7];
  const float* bv = (const float*)d_in[8];
  const float* Wc = (const float*)d_in[9];
  const float* bc = (const float*)d_in[10];
  float* out = (float*)d_out;

  __half *pX, *pW;
  float *pO;
  cudaGetSymbolAddress((void**)&pX, g_X);
  cudaGetSymbolAddress((void**)&pW, g_W);
  cudaGetSymbolAddress((void**)&pO, g_O);

  dim3 tpb(256);
  dim3 gg(8, 32);                       // (N/128, M/128)

  cvt_half<<<2048, tpb>>>(q,  pX);
  cvt_half<<<512,  tpb>>>(Wq, pW);
  proj_tc<<<gg, tpb>>>(bq, nullptr, 1);

  cvt_half<<<2048, tpb>>>(k,  pX);
  cvt_half<<<512,  tpb>>>(Wk, pW);
  proj_tc<<<gg, tpb>>>(bk, nullptr, 2);

  cvt_half<<<2048, tpb>>>(v,  pX);
  cvt_half<<<512,  tpb>>>(Wv, pW);
  proj_tc<<<gg, tpb>>>(bv, nullptr, 3);

  score_tc<<<dim3(16, 16, BHc), tpb>>>();
  colsum2<<<dim3(8, BHc), tpb>>>();
  vtrans<<<dim3(32, BHc), tpb>>>();
  attnv_tc<<<dim3(16, BHc), tpb>>>();

  cvt_half<<<2048, tpb>>>(pO, pX);
  cvt_half<<<512,  tpb>>>(Wc, pW);
  proj_tc<<<gg, tpb>>>(bc, out, 0);
}